// round 12
// baseline (speedup 1.0000x reference)
#include <cuda_runtime.h>
#include <cuda_fp16.h>
#include <math.h>
#include <float.h>
#include <stdint.h>

#define BB 16
#define PP 512
#define RR 8192
#define DD 768
#define MM (BB*RR)

#define KT 64                   // k per tile (halfs)
#define NKT (DD/KT)             // 12
#define STG 3
#define HROWB 144               // bytes per smem row (128 data + 16 pad); 16B-aligned
#define STAGE_BYTES (128*HROWB) // 18432 B per operand tile
#define SMEM_BYTES  (STG * 2 * STAGE_BYTES)   // 110592 B; also >= 128*132*4 staging

// ---------------- scratch (no-alloc rule: __device__ globals) ----------------
static __device__ float  g_center[BB*3];
static __device__ float  g_radius[BB];
static __device__ float  g_feat[(size_t)MM*11];
static __device__ int    g_assign[MM];
static __device__ int    g_counts[BB*PP];
static __device__ int    g_order[MM];      // sorted slot -> raw ray index
static __device__ int    g_sdstp[MM];      // sorted slot -> global patch id (b*PP+p)
static __device__ __half g_H[2][(size_t)MM*DD];  // fp16 hidden activations (q, a)
static __device__ __half g_WT[2][DD*DD];         // fp16 transposed K-major layer-2 weights

namespace {
struct ForceModuleLoad {
    ForceModuleLoad() {
        void* p = nullptr;
        cudaGetSymbolAddress(&p, g_H);
        (void)p;
    }
};
static ForceModuleLoad g_force_load;
}

// order-preserving float<->uint encoding for atomicMax on floats
__device__ __forceinline__ unsigned encf(float v) {
    unsigned u = __float_as_uint(v);
    return (u & 0x80000000u) ? ~u : (u | 0x80000000u);
}
__device__ __forceinline__ float decf(unsigned u) {
    return (u & 0x80000000u) ? __uint_as_float(u ^ 0x80000000u)
                             : __uint_as_float(~u);
}
#define ENC_NEG 0x00800000u   // encf(-FLT_MAX)

// GELU via tanh form + HW tanh.approx.f32 (7 instructions).
__device__ __forceinline__ float gelu_fast(float x) {
    float x2 = x * x;
    float a  = fmaf(0.044715f, x2, 1.0f);
    float arg = 0.7978845608028654f * x * a;
    float th;
    asm("tanh.approx.f32 %0, %1;" : "=f"(th) : "f"(arg));
    float hx = 0.5f * x;
    return fmaf(hx, th, hx);
}

#define CP_ASYNC16(dst, src) \
    asm volatile("cp.async.cg.shared.global [%0], [%1], 16;" :: "r"(dst), "l"(src) : "memory")
#define CP_COMMIT() asm volatile("cp.async.commit_group;" ::: "memory")
#define CP_WAIT1()  asm volatile("cp.async.wait_group 1;" ::: "memory")
#define CP_WAIT0()  asm volatile("cp.async.wait_group 0;" ::: "memory")

#define LDSM4(r, addr) \
    asm volatile("ldmatrix.sync.aligned.m8n8.x4.shared.b16 {%0,%1,%2,%3}, [%4];" \
        : "=r"((r)[0]), "=r"((r)[1]), "=r"((r)[2]), "=r"((r)[3]) : "r"(addr))

#define MMA16816(acc, a, b0, b1) \
    asm volatile( \
        "mma.sync.aligned.m16n8k16.row.col.f32.f16.f16.f32 " \
        "{%0,%1,%2,%3}, {%4,%5,%6,%7}, {%8,%9}, {%0,%1,%2,%3};\n" \
        : "+f"((acc)[0]), "+f"((acc)[1]), "+f"((acc)[2]), "+f"((acc)[3]) \
        : "r"((a)[0]), "r"((a)[1]), "r"((a)[2]), "r"((a)[3]), "r"(b0), "r"(b1))

// ---------------- K0: prep = proxy (blocks 0..15) + weight transposes + zero counts ----
__global__ __launch_bounds__(256)
void prep_kernel(const float* __restrict__ centers,
                 const float* __restrict__ Wq2, const float* __restrict__ Wa2) {
    const int blk = blockIdx.x;
    if (blk < BB) {
        const int b = blk;
        const int tid = threadIdx.x;
        __shared__ float sx[256], sy[256], sz[256];
        float x0 = centers[(b*PP + tid)*3 + 0];
        float y0 = centers[(b*PP + tid)*3 + 1];
        float z0 = centers[(b*PP + tid)*3 + 2];
        float x1 = centers[(b*PP + tid + 256)*3 + 0];
        float y1 = centers[(b*PP + tid + 256)*3 + 1];
        float z1 = centers[(b*PP + tid + 256)*3 + 2];
        sx[tid] = x0 + x1; sy[tid] = y0 + y1; sz[tid] = z0 + z1;
        g_counts[b*PP + tid] = 0;
        g_counts[b*PP + tid + 256] = 0;
        __syncthreads();
        for (int s = 128; s > 0; s >>= 1) {
            if (tid < s) { sx[tid] += sx[tid+s]; sy[tid] += sy[tid+s]; sz[tid] += sz[tid+s]; }
            __syncthreads();
        }
        __shared__ float cx, cy, cz;
        if (tid == 0) { cx = sx[0]*(1.0f/PP); cy = sy[0]*(1.0f/PP); cz = sz[0]*(1.0f/PP); }
        __syncthreads();
        float dx0 = x0-cx, dy0 = y0-cy, dz0 = z0-cz;
        float dx1 = x1-cx, dy1 = y1-cy, dz1 = z1-cz;
        sx[tid] = fmaxf(sqrtf(dx0*dx0 + dy0*dy0 + dz0*dz0),
                        sqrtf(dx1*dx1 + dy1*dy1 + dz1*dz1));
        __syncthreads();
        for (int s = 128; s > 0; s >>= 1) {
            if (tid < s) sx[tid] = fmaxf(sx[tid], sx[tid+s]);
            __syncthreads();
        }
        if (tid == 0) {
            g_center[b*3+0] = cx; g_center[b*3+1] = cy; g_center[b*3+2] = cz;
            g_radius[b] = fmaxf(sx[0], 0.001f) * 1.05f;
        }
    } else {
        // transpose + fp16-round: 576 tiles (32x32) per weight
        int ti = blk - BB;
        int wsel = (ti >= 576) ? 1 : 0;
        if (wsel) ti -= 576;
        const float* __restrict__ W = wsel ? Wa2 : Wq2;
        __half* __restrict__ WT = g_WT[wsel];
        const int bx = ti % 24, by = ti / 24;
        const int tx = threadIdx.x & 31, ty = threadIdx.x >> 5;  // 32x8
        __shared__ float tile[32][33];
        int x = bx*32 + tx;   // n
        int y = by*32 + ty;   // k
        #pragma unroll
        for (int j = 0; j < 32; j += 8)
            tile[ty + j][tx] = W[(size_t)(y + j)*DD + x];
        __syncthreads();
        int k = by*32 + tx;
        int n = bx*32 + ty;
        #pragma unroll
        for (int j = 0; j < 32; j += 8)
            WT[(size_t)(n + j)*DD + k] = __float2half_rn(tile[tx][ty + j]);
    }
}

// ---------------- K1: anchor + argmin + raw features + counts ----------------
__global__ void ray_kernel(const float* __restrict__ centers,
                           const float* __restrict__ ray_o,
                           const float* __restrict__ ray_d,
                           const float* __restrict__ ray_t,
                           const float* __restrict__ ray_hit,
                           const float* __restrict__ ray_n) {
    const int b = blockIdx.y;
    const int r = blockIdx.x * 256 + threadIdx.x;
    __shared__ float scx[PP], scy[PP], scz[PP], scc[PP];
    for (int p = threadIdx.x; p < PP; p += 256) {
        float x = centers[(b*PP + p)*3 + 0];
        float y = centers[(b*PP + p)*3 + 1];
        float z = centers[(b*PP + p)*3 + 2];
        scx[p] = x; scy[p] = y; scz[p] = z;
        scc[p] = x*x + y*y + z*z;
    }
    __syncthreads();

    const int gr = b*RR + r;
    float ox = ray_o[gr*3+0], oy = ray_o[gr*3+1], oz = ray_o[gr*3+2];
    float dx = ray_d[gr*3+0], dy = ray_d[gr*3+1], dz = ray_d[gr*3+2];
    float cx = g_center[b*3+0], cy = g_center[b*3+1], cz = g_center[b*3+2];
    float rad = g_radius[b];

    float ocx = ox - cx, ocy = oy - cy, ocz = oz - cz;
    float a  = dx*dx + dy*dy + dz*dz;
    float bq = 2.0f * (ocx*dx + ocy*dy + ocz*dz);
    float cq = (ocx*ocx + ocy*ocy + ocz*ocz) - rad*rad;
    float disc = bq*bq - 4.0f*a*cq;
    bool  has_real = disc > 0.0f;
    float sd = sqrtf(fmaxf(disc, 0.0f));
    float den = 2.0f*a + 1e-6f;
    float t1 = (-bq - sd) / den;
    float t2 = (-bq + sd) / den;
    float t_pos = (t1 > 1e-6f) ? t1 : ((t2 > 1e-6f) ? t2 : 0.0f);
    float t_cl = fmaxf(-bq / den, 0.0f);
    float t = ((t_pos > 0.0f) && has_real) ? t_pos : t_cl;
    float ax = ox + t*dx, ay = oy + t*dy, az = oz + t*dz;

    float aa = ax*ax + ay*ay + az*az;
    float best = 3.402823466e+38f;
    int bi = 0;
    #pragma unroll 4
    for (int p = 0; p < PP; ++p) {
        float dot = ax*scx[p] + ay*scy[p] + az*scz[p];
        float v = aa + scc[p] - 2.0f*dot;
        if (v < best) { best = v; bi = p; }
    }

    float rx = ax - scx[bi], ry = ay - scy[bi], rz = az - scz[bi];
    float* f = &g_feat[(size_t)gr * 11];
    f[0] = rx; f[1] = ry; f[2] = rz;
    f[3] = dx; f[4] = dy; f[5] = dz;
    f[6] = ray_hit[gr];
    f[7] = ray_t[gr];
    f[8] = ray_n[gr*3+0]; f[9] = ray_n[gr*3+1]; f[10] = ray_n[gr*3+2];
    g_assign[gr] = bi;
    atomicAdd(&g_counts[b*PP + bi], 1);
}

// ---------------- K2: per-batch counting-sort scan + scatter ----------------
__global__ __launch_bounds__(512)
void scan_kernel() {
    const int b = blockIdx.x;
    const int tid = threadIdx.x;   // 512
    __shared__ int scur[PP];
    __shared__ int spfx[PP];
    spfx[tid] = g_counts[b*PP + tid];
    __syncthreads();
    if (tid == 0) {
        int run = 0;
        for (int p = 0; p < PP; ++p) {
            int c = spfx[p];
            scur[p] = b*RR + run;
            run += c;
        }
    }
    __syncthreads();
    for (int r = tid; r < RR; r += 512) {
        int gr = b*RR + r;
        int bi = g_assign[gr];
        int slot = atomicAdd(&scur[bi], 1);
        g_order[slot] = gr;
        g_sdstp[slot] = b*PP + bi;
    }
}

// ---------------- K3: layer-1 (q AND a) + GELU -> g_H[0], g_H[1] (fp16) --------------
__global__ __launch_bounds__(384)
void mlp1_kernel(const float* __restrict__ Wq1, const float* __restrict__ bq1,
                 const float* __restrict__ Wa1, const float* __restrict__ ba1,
                 unsigned* __restrict__ outEnc) {
    const int rowBase = blockIdx.x * 32;
    const int tid = threadIdx.x;     // 384; each thread handles cols (2*tid, 2*tid+1)
    {   // fold outEnc init into this kernel (runs before any gemm)
        size_t gtid = (size_t)blockIdx.x * 384 + tid;
        const size_t tot = (size_t)2*BB*PP*DD;
        const size_t stride = (size_t)(MM/32) * 384;
        for (size_t i = gtid; i < tot; i += stride) outEnc[i] = ENC_NEG;
    }
    __shared__ float sfeat[32*11];
    if (tid < 352) sfeat[tid] = g_feat[(size_t)rowBase*11 + tid];

    const int c0 = tid*2;
    float wq0[6], wq1[6], wa0[11], wa1[11];
    #pragma unroll
    for (int k = 0; k < 6; ++k) {
        wq0[k] = Wq1[k*DD + c0];
        wq1[k] = Wq1[k*DD + c0 + 1];
    }
    #pragma unroll
    for (int k = 0; k < 11; ++k) {
        wa0[k] = Wa1[k*DD + c0];
        wa1[k] = Wa1[k*DD + c0 + 1];
    }
    const float bq0 = bq1[c0], bq1v = bq1[c0 + 1];
    const float ba0 = ba1[c0], ba1v = ba1[c0 + 1];
    __syncthreads();

    #pragma unroll 2
    for (int r = 0; r < 32; ++r) {
        const float* f = &sfeat[r*11];
        float q0 = bq0, q1 = bq1v, a0 = ba0, a1 = ba1v;
        #pragma unroll
        for (int k = 0; k < 6; ++k) {
            float fv = f[k];
            q0 = fmaf(fv, wq0[k], q0);
            q1 = fmaf(fv, wq1[k], q1);
            a0 = fmaf(fv, wa0[k], a0);
            a1 = fmaf(fv, wa1[k], a1);
        }
        #pragma unroll
        for (int k = 6; k < 11; ++k) {
            float fv = f[k];
            a0 = fmaf(fv, wa0[k], a0);
            a1 = fmaf(fv, wa1[k], a1);
        }
        size_t off = (size_t)(rowBase + r)*DD + c0;
        *reinterpret_cast<__half2*>(&g_H[0][off]) =
            __floats2half2_rn(gelu_fast(q0), gelu_fast(q1));
        *reinterpret_cast<__half2*>(&g_H[1][off]) =
            __floats2half2_rn(gelu_fast(a0), gelu_fast(a1));
    }
}

// ---------------- K4: layer-2 fp16 mma GEMM, 4 warps x (64x64 tile), 2 CTA/SM --------
// grid = (DD/128 [N, fastest], MM/128 [M, sorted rows], 2 [q,a]); 128 threads.
// B fragments reused across 4 M-frags -> fragment traffic 0.092 B/MAC (< crossbar limit).
__global__ __launch_bounds__(128, 2)
void gemm_kernel(const float* __restrict__ bq2, const float* __restrict__ ba2,
                 unsigned* __restrict__ outEnc) {
    extern __shared__ float smem[];   // STG stages x (A | B) 18432B each; reused as staging
    __shared__ int   srow[128];
    __shared__ int   sdstp[128];
    __shared__ float sb2[128];

    const int tid = threadIdx.x;
    const int wsel = blockIdx.z;
    const int rowBase = blockIdx.y * 128;
    const int colBase = blockIdx.x * 128;
    const __half* __restrict__ H  = g_H[wsel];
    const __half* __restrict__ WT = g_WT[wsel];
    const float* __restrict__ b2 = wsel ? ba2 : bq2;
    unsigned* __restrict__ outp = outEnc + (size_t)wsel*BB*PP*DD;
    const uint32_t sbase = (uint32_t)__cvta_generic_to_shared(smem);

    {
        srow[tid]  = g_order[rowBase + tid];
        sdstp[tid] = g_sdstp[rowBase + tid];
        sb2[tid]   = b2[colBase + tid];
    }
    __syncthreads();

    // stage loader: 8 A + 8 B cp.async (16B) per thread (128 threads)
    auto load_stage = [&](int s, int kt) {
        const uint32_t aB = sbase + (uint32_t)s * (2*STAGE_BYTES);
        const uint32_t bB = aB + STAGE_BYTES;
        const __half* bSrc = WT + (size_t)colBase*DD + kt*KT;
        #pragma unroll
        for (int i = 0; i < 8; ++i) {
            int idx = tid + i*128;          // 0..1023
            int r = idx >> 3, c = idx & 7;
            const __half* aSrc = H + (size_t)srow[r]*DD + kt*KT + c*8;
            CP_ASYNC16(aB + (uint32_t)(r*HROWB + c*16), aSrc);
        }
        #pragma unroll
        for (int i = 0; i < 8; ++i) {
            int idx = tid + i*128;
            int r = idx >> 3, c = idx & 7;
            CP_ASYNC16(bB + (uint32_t)(r*HROWB + c*16), bSrc + (size_t)r*DD + c*8);
        }
    };

    // prologue: stages 0,1
    load_stage(0, 0); CP_COMMIT();
    load_stage(1, 1); CP_COMMIT();

    const int warp = tid >> 5, lane = tid & 31;
    const int g = lane >> 2, t = lane & 3;
    const int mw = (warp & 1) * 64;   // 2 warps along M (64 rows each)
    const int nw = (warp >> 1) * 64;  // 2 warps along N (64 cols each)
    const int lrow = ((lane >> 3) & 1) * 8 + (lane & 7);
    const int lkof = (lane >> 4) * 16;

    float acc[4][8][4];
    #pragma unroll
    for (int mf = 0; mf < 4; ++mf)
        #pragma unroll
        for (int nf = 0; nf < 8; ++nf)
            #pragma unroll
            for (int q = 0; q < 4; ++q) acc[mf][nf][q] = 0.0f;

    int sc = 0;                      // stage being computed (0..STG-1)
    for (int kt = 0; kt < NKT; ++kt) {
        if (kt + 2 < NKT) CP_WAIT1(); else CP_WAIT0();
        __syncthreads();             // licenses overwriting stage computed last iter
        if (kt + 2 < NKT) {
            int sl = sc + 2; if (sl >= STG) sl -= STG;
            load_stage(sl, kt + 2);
            CP_COMMIT();
        }

        const uint32_t aS = sbase + (uint32_t)sc * (2*STAGE_BYTES);
        const uint32_t bS = aS + STAGE_BYTES;
        const uint32_t aAddr = aS + (uint32_t)((mw + lrow)*HROWB + lkof);
        const uint32_t bAddr = bS + (uint32_t)((nw + lrow)*HROWB + lkof);

        #pragma unroll
        for (int ks = 0; ks < 4; ++ks) {          // four k16 steps per k64 tile
            const uint32_t ko = (uint32_t)(ks*32);
            uint32_t am[4][4], bm[4][4];
            #pragma unroll
            for (int mf = 0; mf < 4; ++mf)
                LDSM4(am[mf], aAddr + (uint32_t)(mf*16*HROWB) + ko);
            #pragma unroll
            for (int p = 0; p < 4; ++p)
                LDSM4(bm[p], bAddr + (uint32_t)(p*16*HROWB) + ko);
            #pragma unroll
            for (int p = 0; p < 4; ++p) {
                #pragma unroll
                for (int mf = 0; mf < 4; ++mf) {
                    MMA16816(acc[mf][2*p],     am[mf], bm[p][0], bm[p][2]);
                    MMA16816(acc[mf][2*p + 1], am[mf], bm[p][1], bm[p][3]);
                }
            }
        }
        if (++sc == STG) sc = 0;
    }

    // ---- epilogue: stage accs (+bias) in smem, segmented max per column ----
    __syncthreads();
    float* Es = smem;   // 128 x 132
    #pragma unroll
    for (int mf = 0; mf < 4; ++mf) {
        int r0 = mw + mf*16 + g;
        #pragma unroll
        for (int nf = 0; nf < 8; ++nf) {
            int c0 = nw + (nf >> 1)*16 + (nf & 1)*8 + 2*t;
            Es[r0*132 + c0]         = acc[mf][nf][0] + sb2[c0];
            Es[r0*132 + c0 + 1]     = acc[mf][nf][1] + sb2[c0 + 1];
            Es[(r0+8)*132 + c0]     = acc[mf][nf][2] + sb2[c0];
            Es[(r0+8)*132 + c0 + 1] = acc[mf][nf][3] + sb2[c0 + 1];
        }
    }
    __syncthreads();

    {
        const int col = tid;          // 128 threads = 1 per column
        int cur = sdstp[0];
        float m = -FLT_MAX;
        #pragma unroll 8
        for (int r = 0; r < 128; ++r) {
            int d = sdstp[r];
            float v = Es[r*132 + col];
            if (d != cur) {
                atomicMax(outp + (size_t)cur*DD + colBase + col, encf(m));
                cur = d; m = v;
            } else {
                m = fmaxf(m, v);
            }
        }
        atomicMax(outp + (size_t)cur*DD + colBase + col, encf(m));
    }
}

// ---------------- K5: decode + mask + has_ray ----------------
__global__ void final_kernel(unsigned* __restrict__ outEnc, float* __restrict__ out) {
    int i = blockIdx.x * 256 + threadIdx.x;
    if (i < BB*PP*DD) {
        int bp = i / DD;
        bool has = g_counts[bp] > 0;
        unsigned uq = outEnc[i];
        out[i] = has ? decf(uq) : 0.0f;
        unsigned ua = outEnc[(size_t)BB*PP*DD + i];
        out[(size_t)BB*PP*DD + i] = has ? decf(ua) : 0.0f;
    }
    if (i < BB*PP) {
        out[(size_t)2*BB*PP*DD + i] = (g_counts[i] > 0) ? 1.0f : 0.0f;
    }
}

// ---------------- launch ----------------
extern "C" void kernel_launch(void* const* d_in, const int* in_sizes, int n_in,
                              void* d_out, int out_size) {
    (void)in_sizes; (void)n_in; (void)out_size;
    const float* centers = (const float*)d_in[0];
    const float* ray_o   = (const float*)d_in[1];
    const float* ray_d   = (const float*)d_in[2];
    const float* ray_t   = (const float*)d_in[3];
    const float* ray_hit = (const float*)d_in[4];
    const float* ray_n   = (const float*)d_in[5];
    const float* Wq1 = (const float*)d_in[6];
    const float* bq1 = (const float*)d_in[7];
    const float* Wq2 = (const float*)d_in[8];
    const float* bq2 = (const float*)d_in[9];
    const float* Wa1 = (const float*)d_in[10];
    const float* ba1 = (const float*)d_in[11];
    const float* Wa2 = (const float*)d_in[12];
    const float* ba2 = (const float*)d_in[13];

    unsigned* outEnc = (unsigned*)d_out;
    float*    out    = (float*)d_out;

    static bool attr_set = false;
    if (!attr_set) {
        cudaFuncSetAttribute(gemm_kernel, cudaFuncAttributeMaxDynamicSharedMemorySize, SMEM_BYTES);
        attr_set = true;
    }

    prep_kernel<<<BB + 2*576, 256>>>(centers, Wq2, Wa2);
    dim3 gridRay(RR/256, BB);
    ray_kernel<<<gridRay, 256>>>(centers, ray_o, ray_d, ray_t, ray_hit, ray_n);
    scan_kernel<<<BB, 512>>>();

    mlp1_kernel<<<MM/32, 384>>>(Wq1, bq1, Wa1, ba1, outEnc);

    dim3 gridG(DD/128, MM/128, 2);   // x = N (fastest, L2 A-reuse), z = {q, a}
    gemm_kernel<<<gridG, 128, SMEM_BYTES>>>(bq2, ba2, outEnc);

    final_kernel<<<(BB*PP*DD + 255)/256, 256>>>(outEnc, out);
}

// round 13
// speedup vs baseline: 1.0614x; 1.0614x over previous
#include <cuda_runtime.h>
#include <cuda_fp16.h>
#include <math.h>
#include <float.h>
#include <stdint.h>

#define BB 16
#define PP 512
#define RR 8192
#define DD 768
#define MM (BB*RR)

#define KT 64                   // k per tile (halfs)
#define NKT (DD/KT)             // 12
#define STG 3
#define HROWB 144               // bytes per smem row (128 data + 16 pad); 16B-aligned
#define STAGE_BYTES (128*HROWB) // 18432 B per operand tile
#define SMEM_BYTES  (STG * 2 * STAGE_BYTES)   // 110592 B; also >= 128*132*4 staging

// ---------------- scratch (no-alloc rule: __device__ globals) ----------------
static __device__ float  g_center[BB*3];
static __device__ float  g_radius[BB];
static __device__ float  g_feat[(size_t)MM*11];
static __device__ int    g_assign[MM];
static __device__ int    g_counts[BB*PP];
static __device__ int    g_order[MM];      // sorted slot -> raw ray index
static __device__ int    g_sdstp[MM];      // sorted slot -> global patch id (b*PP+p)
static __device__ __half g_H[2][(size_t)MM*DD];  // fp16 hidden activations (q, a)
static __device__ __half g_WT[2][DD*DD];         // fp16 transposed K-major layer-2 weights

namespace {
struct ForceModuleLoad {
    ForceModuleLoad() {
        void* p = nullptr;
        cudaGetSymbolAddress(&p, g_H);
        (void)p;
    }
};
static ForceModuleLoad g_force_load;
}

// order-preserving float<->uint encoding for atomicMax on floats
__device__ __forceinline__ unsigned encf(float v) {
    unsigned u = __float_as_uint(v);
    return (u & 0x80000000u) ? ~u : (u | 0x80000000u);
}
__device__ __forceinline__ float decf(unsigned u) {
    return (u & 0x80000000u) ? __uint_as_float(u ^ 0x80000000u)
                             : __uint_as_float(~u);
}
#define ENC_NEG 0x00800000u   // encf(-FLT_MAX)

// GELU via tanh form + HW tanh.approx.f32 (7 instructions).
__device__ __forceinline__ float gelu_fast(float x) {
    float x2 = x * x;
    float a  = fmaf(0.044715f, x2, 1.0f);
    float arg = 0.7978845608028654f * x * a;
    float th;
    asm("tanh.approx.f32 %0, %1;" : "=f"(th) : "f"(arg));
    float hx = 0.5f * x;
    return fmaf(hx, th, hx);
}

#define CP_ASYNC16(dst, src) \
    asm volatile("cp.async.cg.shared.global [%0], [%1], 16;" :: "r"(dst), "l"(src) : "memory")
#define CP_COMMIT() asm volatile("cp.async.commit_group;" ::: "memory")
#define CP_WAIT1()  asm volatile("cp.async.wait_group 1;" ::: "memory")
#define CP_WAIT0()  asm volatile("cp.async.wait_group 0;" ::: "memory")

#define LDSM4(r, addr) \
    asm volatile("ldmatrix.sync.aligned.m8n8.x4.shared.b16 {%0,%1,%2,%3}, [%4];" \
        : "=r"((r)[0]), "=r"((r)[1]), "=r"((r)[2]), "=r"((r)[3]) : "r"(addr))

#define MMA16816(acc, a, b0, b1) \
    asm volatile( \
        "mma.sync.aligned.m16n8k16.row.col.f32.f16.f16.f32 " \
        "{%0,%1,%2,%3}, {%4,%5,%6,%7}, {%8,%9}, {%0,%1,%2,%3};\n" \
        : "+f"((acc)[0]), "+f"((acc)[1]), "+f"((acc)[2]), "+f"((acc)[3]) \
        : "r"((a)[0]), "r"((a)[1]), "r"((a)[2]), "r"((a)[3]), "r"(b0), "r"(b1))

// ---------------- K0: prep = proxy (blocks 0..15) + weight transposes + init ---------
__global__ __launch_bounds__(256)
void prep_kernel(const float* __restrict__ centers,
                 const float* __restrict__ Wq2, const float* __restrict__ Wa2,
                 unsigned* __restrict__ outEnc) {
    const int blk = blockIdx.x;
    // grid-stride uint4 init of outEnc (runs strictly before any gemm)
    {
        const size_t nvec = (size_t)2*BB*PP*DD / 4;   // 3,145,728 uint4
        uint4 fill = make_uint4(ENC_NEG, ENC_NEG, ENC_NEG, ENC_NEG);
        size_t stride = (size_t)gridDim.x * 256;
        for (size_t i = (size_t)blk*256 + threadIdx.x; i < nvec; i += stride)
            reinterpret_cast<uint4*>(outEnc)[i] = fill;
    }
    if (blk < BB) {
        const int b = blk;
        const int tid = threadIdx.x;
        __shared__ float sx[256], sy[256], sz[256];
        float x0 = centers[(b*PP + tid)*3 + 0];
        float y0 = centers[(b*PP + tid)*3 + 1];
        float z0 = centers[(b*PP + tid)*3 + 2];
        float x1 = centers[(b*PP + tid + 256)*3 + 0];
        float y1 = centers[(b*PP + tid + 256)*3 + 1];
        float z1 = centers[(b*PP + tid + 256)*3 + 2];
        sx[tid] = x0 + x1; sy[tid] = y0 + y1; sz[tid] = z0 + z1;
        g_counts[b*PP + tid] = 0;
        g_counts[b*PP + tid + 256] = 0;
        __syncthreads();
        for (int s = 128; s > 0; s >>= 1) {
            if (tid < s) { sx[tid] += sx[tid+s]; sy[tid] += sy[tid+s]; sz[tid] += sz[tid+s]; }
            __syncthreads();
        }
        __shared__ float cx, cy, cz;
        if (tid == 0) { cx = sx[0]*(1.0f/PP); cy = sy[0]*(1.0f/PP); cz = sz[0]*(1.0f/PP); }
        __syncthreads();
        float dx0 = x0-cx, dy0 = y0-cy, dz0 = z0-cz;
        float dx1 = x1-cx, dy1 = y1-cy, dz1 = z1-cz;
        sx[tid] = fmaxf(sqrtf(dx0*dx0 + dy0*dy0 + dz0*dz0),
                        sqrtf(dx1*dx1 + dy1*dy1 + dz1*dz1));
        __syncthreads();
        for (int s = 128; s > 0; s >>= 1) {
            if (tid < s) sx[tid] = fmaxf(sx[tid], sx[tid+s]);
            __syncthreads();
        }
        if (tid == 0) {
            g_center[b*3+0] = cx; g_center[b*3+1] = cy; g_center[b*3+2] = cz;
            g_radius[b] = fmaxf(sx[0], 0.001f) * 1.05f;
        }
    } else {
        // transpose + fp16-round: 576 tiles (32x32) per weight
        int ti = blk - BB;
        int wsel = (ti >= 576) ? 1 : 0;
        if (wsel) ti -= 576;
        const float* __restrict__ W = wsel ? Wa2 : Wq2;
        __half* __restrict__ WT = g_WT[wsel];
        const int bx = ti % 24, by = ti / 24;
        const int tx = threadIdx.x & 31, ty = threadIdx.x >> 5;  // 32x8
        __shared__ float tile[32][33];
        int x = bx*32 + tx;   // n
        int y = by*32 + ty;   // k
        #pragma unroll
        for (int j = 0; j < 32; j += 8)
            tile[ty + j][tx] = W[(size_t)(y + j)*DD + x];
        __syncthreads();
        int k = by*32 + tx;
        int n = bx*32 + ty;
        #pragma unroll
        for (int j = 0; j < 32; j += 8)
            WT[(size_t)(n + j)*DD + k] = __float2half_rn(tile[tx][ty + j]);
    }
}

// ---------------- K1: anchor + argmin + raw features + counts ----------------
__global__ void ray_kernel(const float* __restrict__ centers,
                           const float* __restrict__ ray_o,
                           const float* __restrict__ ray_d,
                           const float* __restrict__ ray_t,
                           const float* __restrict__ ray_hit,
                           const float* __restrict__ ray_n) {
    const int b = blockIdx.y;
    const int r = blockIdx.x * 256 + threadIdx.x;
    __shared__ float scx[PP], scy[PP], scz[PP], scc[PP];
    for (int p = threadIdx.x; p < PP; p += 256) {
        float x = centers[(b*PP + p)*3 + 0];
        float y = centers[(b*PP + p)*3 + 1];
        float z = centers[(b*PP + p)*3 + 2];
        scx[p] = x; scy[p] = y; scz[p] = z;
        scc[p] = x*x + y*y + z*z;
    }
    __syncthreads();

    const int gr = b*RR + r;
    float ox = ray_o[gr*3+0], oy = ray_o[gr*3+1], oz = ray_o[gr*3+2];
    float dx = ray_d[gr*3+0], dy = ray_d[gr*3+1], dz = ray_d[gr*3+2];
    float cx = g_center[b*3+0], cy = g_center[b*3+1], cz = g_center[b*3+2];
    float rad = g_radius[b];

    float ocx = ox - cx, ocy = oy - cy, ocz = oz - cz;
    float a  = dx*dx + dy*dy + dz*dz;
    float bq = 2.0f * (ocx*dx + ocy*dy + ocz*dz);
    float cq = (ocx*ocx + ocy*ocy + ocz*ocz) - rad*rad;
    float disc = bq*bq - 4.0f*a*cq;
    bool  has_real = disc > 0.0f;
    float sd = sqrtf(fmaxf(disc, 0.0f));
    float den = 2.0f*a + 1e-6f;
    float t1 = (-bq - sd) / den;
    float t2 = (-bq + sd) / den;
    float t_pos = (t1 > 1e-6f) ? t1 : ((t2 > 1e-6f) ? t2 : 0.0f);
    float t_cl = fmaxf(-bq / den, 0.0f);
    float t = ((t_pos > 0.0f) && has_real) ? t_pos : t_cl;
    float ax = ox + t*dx, ay = oy + t*dy, az = oz + t*dz;

    float aa = ax*ax + ay*ay + az*az;
    float best = 3.402823466e+38f;
    int bi = 0;
    #pragma unroll 4
    for (int p = 0; p < PP; ++p) {
        float dot = ax*scx[p] + ay*scy[p] + az*scz[p];
        float v = aa + scc[p] - 2.0f*dot;
        if (v < best) { best = v; bi = p; }
    }

    float rx = ax - scx[bi], ry = ay - scy[bi], rz = az - scz[bi];
    float* f = &g_feat[(size_t)gr * 11];
    f[0] = rx; f[1] = ry; f[2] = rz;
    f[3] = dx; f[4] = dy; f[5] = dz;
    f[6] = ray_hit[gr];
    f[7] = ray_t[gr];
    f[8] = ray_n[gr*3+0]; f[9] = ray_n[gr*3+1]; f[10] = ray_n[gr*3+2];
    g_assign[gr] = bi;
    atomicAdd(&g_counts[b*PP + bi], 1);
}

// ---------------- K2: per-batch counting-sort scan + scatter ----------------
__global__ __launch_bounds__(512)
void scan_kernel() {
    const int b = blockIdx.x;
    const int tid = threadIdx.x;   // 512
    __shared__ int scur[PP];
    __shared__ int spfx[PP];
    spfx[tid] = g_counts[b*PP + tid];
    __syncthreads();
    if (tid == 0) {
        int run = 0;
        for (int p = 0; p < PP; ++p) {
            int c = spfx[p];
            scur[p] = b*RR + run;
            run += c;
        }
    }
    __syncthreads();
    for (int r = tid; r < RR; r += 512) {
        int gr = b*RR + r;
        int bi = g_assign[gr];
        int slot = atomicAdd(&scur[bi], 1);
        g_order[slot] = gr;
        g_sdstp[slot] = b*PP + bi;
    }
}

// ---------------- K3: layer-1 (q AND a) + GELU -> g_H[0], g_H[1] (fp16) --------------
__global__ __launch_bounds__(384)
void mlp1_kernel(const float* __restrict__ Wq1, const float* __restrict__ bq1,
                 const float* __restrict__ Wa1, const float* __restrict__ ba1) {
    const int rowBase = blockIdx.x * 32;
    const int tid = threadIdx.x;     // 384; each thread handles cols (2*tid, 2*tid+1)
    __shared__ float sfeat[32*11];
    if (tid < 352) sfeat[tid] = g_feat[(size_t)rowBase*11 + tid];

    const int c0 = tid*2;
    float wq0[6], wq1[6], wa0[11], wa1[11];
    #pragma unroll
    for (int k = 0; k < 6; ++k) {
        wq0[k] = Wq1[k*DD + c0];
        wq1[k] = Wq1[k*DD + c0 + 1];
    }
    #pragma unroll
    for (int k = 0; k < 11; ++k) {
        wa0[k] = Wa1[k*DD + c0];
        wa1[k] = Wa1[k*DD + c0 + 1];
    }
    const float bq0 = bq1[c0], bq1v = bq1[c0 + 1];
    const float ba0 = ba1[c0], ba1v = ba1[c0 + 1];
    __syncthreads();

    #pragma unroll 2
    for (int r = 0; r < 32; ++r) {
        const float* f = &sfeat[r*11];
        float q0 = bq0, q1 = bq1v, a0 = ba0, a1 = ba1v;
        #pragma unroll
        for (int k = 0; k < 6; ++k) {
            float fv = f[k];
            q0 = fmaf(fv, wq0[k], q0);
            q1 = fmaf(fv, wq1[k], q1);
            a0 = fmaf(fv, wa0[k], a0);
            a1 = fmaf(fv, wa1[k], a1);
        }
        #pragma unroll
        for (int k = 6; k < 11; ++k) {
            float fv = f[k];
            a0 = fmaf(fv, wa0[k], a0);
            a1 = fmaf(fv, wa1[k], a1);
        }
        size_t off = (size_t)(rowBase + r)*DD + c0;
        *reinterpret_cast<__half2*>(&g_H[0][off]) =
            __floats2half2_rn(gelu_fast(q0), gelu_fast(q1));
        *reinterpret_cast<__half2*>(&g_H[1][off]) =
            __floats2half2_rn(gelu_fast(a0), gelu_fast(a1));
    }
}

// ---------------- K4: layer-2 fp16 mma GEMM (both MLPs, grid.z) + segmented max ------
// grid = (DD/128 [N, fastest], MM/128 [M, sorted rows], 2 [q,a]); 256 threads; 2 CTA/SM.
__global__ __launch_bounds__(256, 2)
void gemm_kernel(const float* __restrict__ bq2, const float* __restrict__ ba2,
                 unsigned* __restrict__ outEnc) {
    extern __shared__ float smem[];   // STG stages x (A | B) 18432B each; reused as staging
    __shared__ int   srow[128];
    __shared__ int   sdstp[128];
    __shared__ float sb2[128];

    const int tid = threadIdx.x;
    const int wsel = blockIdx.z;
    const int rowBase = blockIdx.y * 128;
    const int colBase = blockIdx.x * 128;
    const __half* __restrict__ H  = g_H[wsel];
    const __half* __restrict__ WT = g_WT[wsel];
    const float* __restrict__ b2 = wsel ? ba2 : bq2;
    unsigned* __restrict__ outp = outEnc + (size_t)wsel*BB*PP*DD;
    const uint32_t sbase = (uint32_t)__cvta_generic_to_shared(smem);

    if (tid < 128) {
        srow[tid]  = g_order[rowBase + tid];
        sdstp[tid] = g_sdstp[rowBase + tid];
        sb2[tid]   = b2[colBase + tid];
    }
    __syncthreads();

    // stage loader: 4 A + 4 B cp.async (16B) per thread (K=64: 8 chunks/row)
    auto load_stage = [&](int s, int kt) {
        const uint32_t aB = sbase + (uint32_t)s * (2*STAGE_BYTES);
        const uint32_t bB = aB + STAGE_BYTES;
        const __half* bSrc = WT + (size_t)colBase*DD + kt*KT;
        #pragma unroll
        for (int i = 0; i < 4; ++i) {
            int idx = tid + i*256;          // 0..1023
            int r = idx >> 3, c = idx & 7;
            const __half* aSrc = H + (size_t)srow[r]*DD + kt*KT + c*8;
            CP_ASYNC16(aB + (uint32_t)(r*HROWB + c*16), aSrc);
        }
        #pragma unroll
        for (int i = 0; i < 4; ++i) {
            int idx = tid + i*256;
            int r = idx >> 3, c = idx & 7;
            CP_ASYNC16(bB + (uint32_t)(r*HROWB + c*16), bSrc + (size_t)r*DD + c*8);
        }
    };

    // prologue: stages 0,1
    load_stage(0, 0); CP_COMMIT();
    load_stage(1, 1); CP_COMMIT();

    const int warp = tid >> 5, lane = tid & 31;
    const int g = lane >> 2, t = lane & 3;
    const int mw = (warp & 3) * 32;   // 4 warps along M
    const int nw = (warp >> 2) * 64;  // 2 warps along N
    const int lrow = ((lane >> 3) & 1) * 8 + (lane & 7);
    const int lkof = (lane >> 4) * 16;

    float acc[2][8][4];
    #pragma unroll
    for (int mf = 0; mf < 2; ++mf)
        #pragma unroll
        for (int nf = 0; nf < 8; ++nf)
            #pragma unroll
            for (int q = 0; q < 4; ++q) acc[mf][nf][q] = 0.0f;

    int sc = 0;                      // stage being computed (0..STG-1)
    for (int kt = 0; kt < NKT; ++kt) {
        if (kt + 2 < NKT) CP_WAIT1(); else CP_WAIT0();
        __syncthreads();             // licenses overwriting stage computed last iter
        if (kt + 2 < NKT) {
            int sl = sc + 2; if (sl >= STG) sl -= STG;
            load_stage(sl, kt + 2);
            CP_COMMIT();
        }

        const uint32_t aS = sbase + (uint32_t)sc * (2*STAGE_BYTES);
        const uint32_t bS = aS + STAGE_BYTES;
        const uint32_t aAddr = aS + (uint32_t)((mw + lrow)*HROWB + lkof);
        const uint32_t bAddr = bS + (uint32_t)((nw + lrow)*HROWB + lkof);

        #pragma unroll
        for (int ks = 0; ks < 4; ++ks) {          // four k16 steps per k64 tile
            const uint32_t ko = (uint32_t)(ks*32);
            uint32_t am[2][4];
            LDSM4(am[0], aAddr + ko);
            LDSM4(am[1], aAddr + 16*HROWB + ko);
            #pragma unroll
            for (int p = 0; p < 4; ++p) {          // 4 n-blocks of 16
                uint32_t bm[4];
                LDSM4(bm, bAddr + (uint32_t)(p*16*HROWB) + ko);
                #pragma unroll
                for (int mf = 0; mf < 2; ++mf) {
                    MMA16816(acc[mf][2*p],     am[mf], bm[0], bm[2]);
                    MMA16816(acc[mf][2*p + 1], am[mf], bm[1], bm[3]);
                }
            }
        }
        if (++sc == STG) sc = 0;
    }

    // ---- epilogue: stage accs (+bias) in smem, segmented max per column ----
    __syncthreads();
    float* Es = smem;   // 128 x 132
    #pragma unroll
    for (int mf = 0; mf < 2; ++mf) {
        int r0 = mw + mf*16 + g;
        #pragma unroll
        for (int nf = 0; nf < 8; ++nf) {
            int c0 = nw + (nf >> 1)*16 + (nf & 1)*8 + 2*t;
            Es[r0*132 + c0]         = acc[mf][nf][0] + sb2[c0];
            Es[r0*132 + c0 + 1]     = acc[mf][nf][1] + sb2[c0 + 1];
            Es[(r0+8)*132 + c0]     = acc[mf][nf][2] + sb2[c0];
            Es[(r0+8)*132 + c0 + 1] = acc[mf][nf][3] + sb2[c0 + 1];
        }
    }
    __syncthreads();

    {
        const int col = tid & 127;
        const int rbase = (tid >> 7) * 64;
        int cur = sdstp[rbase];
        float m = -FLT_MAX;
        #pragma unroll 8
        for (int r = rbase; r < rbase + 64; ++r) {
            int d = sdstp[r];
            float v = Es[r*132 + col];
            if (d != cur) {
                atomicMax(outp + (size_t)cur*DD + colBase + col, encf(m));
                cur = d; m = v;
            } else {
                m = fmaxf(m, v);
            }
        }
        atomicMax(outp + (size_t)cur*DD + colBase + col, encf(m));
    }
}

// ---------------- K5: decode + mask + has_ray ----------------
__global__ void final_kernel(unsigned* __restrict__ outEnc, float* __restrict__ out) {
    int i = blockIdx.x * 256 + threadIdx.x;
    if (i < BB*PP*DD) {
        int bp = i / DD;
        bool has = g_counts[bp] > 0;
        unsigned uq = outEnc[i];
        out[i] = has ? decf(uq) : 0.0f;
        unsigned ua = outEnc[(size_t)BB*PP*DD + i];
        out[(size_t)BB*PP*DD + i] = has ? decf(ua) : 0.0f;
    }
    if (i < BB*PP) {
        out[(size_t)2*BB*PP*DD + i] = (g_counts[i] > 0) ? 1.0f : 0.0f;
    }
}

// ---------------- launch ----------------
extern "C" void kernel_launch(void* const* d_in, const int* in_sizes, int n_in,
                              void* d_out, int out_size) {
    (void)in_sizes; (void)n_in; (void)out_size;
    const float* centers = (const float*)d_in[0];
    const float* ray_o   = (const float*)d_in[1];
    const float* ray_d   = (const float*)d_in[2];
    const float* ray_t   = (const float*)d_in[3];
    const float* ray_hit = (const float*)d_in[4];
    const float* ray_n   = (const float*)d_in[5];
    const float* Wq1 = (const float*)d_in[6];
    const float* bq1 = (const float*)d_in[7];
    const float* Wq2 = (const float*)d_in[8];
    const float* bq2 = (const float*)d_in[9];
    const float* Wa1 = (const float*)d_in[10];
    const float* ba1 = (const float*)d_in[11];
    const float* Wa2 = (const float*)d_in[12];
    const float* ba2 = (const float*)d_in[13];

    unsigned* outEnc = (unsigned*)d_out;
    float*    out    = (float*)d_out;

    static bool attr_set = false;
    if (!attr_set) {
        cudaFuncSetAttribute(gemm_kernel, cudaFuncAttributeMaxDynamicSharedMemorySize, SMEM_BYTES);
        attr_set = true;
    }

    prep_kernel<<<BB + 2*576, 256>>>(centers, Wq2, Wa2, outEnc);
    dim3 gridRay(RR/256, BB);
    ray_kernel<<<gridRay, 256>>>(centers, ray_o, ray_d, ray_t, ray_hit, ray_n);
    scan_kernel<<<BB, 512>>>();

    mlp1_kernel<<<MM/32, 384>>>(Wq1, bq1, Wa1, ba1);

    dim3 gridG(DD/128, MM/128, 2);   // x = N (fastest, L2 A-reuse), z = {q, a}
    gemm_kernel<<<gridG, 256, SMEM_BYTES>>>(bq2, ba2, outEnc);

    final_kernel<<<(BB*PP*DD + 255)/256, 256>>>(outEnc, out);
}

// round 15
// speedup vs baseline: 1.0685x; 1.0067x over previous
#include <cuda_runtime.h>
#include <cuda_fp16.h>
#include <math.h>
#include <float.h>
#include <stdint.h>

#define BB 16
#define PP 512
#define RR 8192
#define DD 768
#define MM (BB*RR)

#define KT 64                   // k per tile (halfs)
#define NKT (DD/KT)             // 12
#define STG 3
#define HROWB 144               // bytes per smem row (128 data + 16 pad); 16B-aligned
#define STAGE_BYTES (128*HROWB) // 18432 B per operand tile
#define SMEM_BYTES  (STG * 2 * STAGE_BYTES)   // 110592 B; also >= 128*132*4 staging

// ---------------- scratch (no-alloc rule: __device__ globals) ----------------
static __device__ float  g_center[BB*3];
static __device__ float  g_radius[BB];
static __device__ float  g_feat[(size_t)MM*11];
static __device__ int    g_assign[MM];
static __device__ int    g_counts[BB*PP];
static __device__ int    g_order[MM];      // sorted slot -> raw ray index
static __device__ int    g_sdstp[MM];      // sorted slot -> global patch id (b*PP+p)
static __device__ __half g_H[2][(size_t)MM*DD];  // fp16 hidden activations (q, a)
static __device__ __half g_WT[2][DD*DD];         // fp16 transposed K-major layer-2 weights

namespace {
struct ForceModuleLoad {
    ForceModuleLoad() {
        void* p = nullptr;
        cudaGetSymbolAddress(&p, g_H);
        (void)p;
    }
};
static ForceModuleLoad g_force_load;
}

// order-preserving float<->uint encoding for atomicMax on floats
__device__ __forceinline__ unsigned encf(float v) {
    unsigned u = __float_as_uint(v);
    return (u & 0x80000000u) ? ~u : (u | 0x80000000u);
}
__device__ __forceinline__ float decf(unsigned u) {
    return (u & 0x80000000u) ? __uint_as_float(u ^ 0x80000000u)
                             : __uint_as_float(~u);
}
#define ENC_NEG 0x00800000u   // encf(-FLT_MAX)

// ---------------- packed f32x2 helpers (sm_100 PTX 8.6) ----------------
typedef unsigned long long u64t;
__device__ __forceinline__ u64t pk2(float lo, float hi) {
    u64t r; asm("mov.b64 %0, {%1, %2};" : "=l"(r) : "f"(lo), "f"(hi)); return r;
}
__device__ __forceinline__ void upk2(float& lo, float& hi, u64t v) {
    asm("mov.b64 {%0, %1}, %2;" : "=f"(lo), "=f"(hi) : "l"(v));
}
#define FFMA2(d, a, b, c) \
    asm("fma.rn.f32x2 %0, %1, %2, %3;" : "=l"(d) : "l"(a), "l"(b), "l"(c))
#define FMUL2(d, a, b) \
    asm("mul.rn.f32x2 %0, %1, %2;" : "=l"(d) : "l"(a), "l"(b))

// Packed GELU (tanh form, HW tanh.approx per lane). Lanes are independent IEEE
// fp32 ops -> bitwise identical to the scalar version.
__device__ __forceinline__ u64t gelu2(u64t x) {
    const u64t c_a   = pk2(0.044715f, 0.044715f);
    const u64t c_one = pk2(1.0f, 1.0f);
    const u64t c_s   = pk2(0.7978845608028654f, 0.7978845608028654f);
    const u64t c_h   = pk2(0.5f, 0.5f);
    u64t x2;  FMUL2(x2, x, x);
    u64t t;   FFMA2(t, c_a, x2, c_one);
    u64t arg; FMUL2(arg, c_s, x); FMUL2(arg, arg, t);
    float a0, a1; upk2(a0, a1, arg);
    float t0, t1;
    asm("tanh.approx.f32 %0, %1;" : "=f"(t0) : "f"(a0));
    asm("tanh.approx.f32 %0, %1;" : "=f"(t1) : "f"(a1));
    u64t th = pk2(t0, t1);
    u64t hx; FMUL2(hx, c_h, x);
    u64t r;  FFMA2(r, hx, th, hx);
    return r;
}

#define CP_ASYNC16(dst, src) \
    asm volatile("cp.async.cg.shared.global [%0], [%1], 16;" :: "r"(dst), "l"(src) : "memory")
#define CP_COMMIT() asm volatile("cp.async.commit_group;" ::: "memory")
#define CP_WAIT1()  asm volatile("cp.async.wait_group 1;" ::: "memory")
#define CP_WAIT0()  asm volatile("cp.async.wait_group 0;" ::: "memory")

#define LDSM4(r, addr) \
    asm volatile("ldmatrix.sync.aligned.m8n8.x4.shared.b16 {%0,%1,%2,%3}, [%4];" \
        : "=r"((r)[0]), "=r"((r)[1]), "=r"((r)[2]), "=r"((r)[3]) : "r"(addr))

#define MMA16816(acc, a, b0, b1) \
    asm volatile( \
        "mma.sync.aligned.m16n8k16.row.col.f32.f16.f16.f32 " \
        "{%0,%1,%2,%3}, {%4,%5,%6,%7}, {%8,%9}, {%0,%1,%2,%3};\n" \
        : "+f"((acc)[0]), "+f"((acc)[1]), "+f"((acc)[2]), "+f"((acc)[3]) \
        : "r"((a)[0]), "r"((a)[1]), "r"((a)[2]), "r"((a)[3]), "r"(b0), "r"(b1))

// ---------------- K0: prep = proxy (blocks 0..15) + weight transposes + init ---------
__global__ __launch_bounds__(256)
void prep_kernel(const float* __restrict__ centers,
                 const float* __restrict__ Wq2, const float* __restrict__ Wa2,
                 unsigned* __restrict__ outEnc) {
    const int blk = blockIdx.x;
    // grid-stride uint4 init of outEnc (runs strictly before any gemm)
    {
        const size_t nvec = (size_t)2*BB*PP*DD / 4;   // 3,145,728 uint4
        uint4 fill = make_uint4(ENC_NEG, ENC_NEG, ENC_NEG, ENC_NEG);
        size_t stride = (size_t)gridDim.x * 256;
        for (size_t i = (size_t)blk*256 + threadIdx.x; i < nvec; i += stride)
            reinterpret_cast<uint4*>(outEnc)[i] = fill;
    }
    if (blk < BB) {
        const int b = blk;
        const int tid = threadIdx.x;
        __shared__ float sx[256], sy[256], sz[256];
        float x0 = centers[(b*PP + tid)*3 + 0];
        float y0 = centers[(b*PP + tid)*3 + 1];
        float z0 = centers[(b*PP + tid)*3 + 2];
        float x1 = centers[(b*PP + tid + 256)*3 + 0];
        float y1 = centers[(b*PP + tid + 256)*3 + 1];
        float z1 = centers[(b*PP + tid + 256)*3 + 2];
        sx[tid] = x0 + x1; sy[tid] = y0 + y1; sz[tid] = z0 + z1;
        g_counts[b*PP + tid] = 0;
        g_counts[b*PP + tid + 256] = 0;
        __syncthreads();
        for (int s = 128; s > 0; s >>= 1) {
            if (tid < s) { sx[tid] += sx[tid+s]; sy[tid] += sy[tid+s]; sz[tid] += sz[tid+s]; }
            __syncthreads();
        }
        __shared__ float cx, cy, cz;
        if (tid == 0) { cx = sx[0]*(1.0f/PP); cy = sy[0]*(1.0f/PP); cz = sz[0]*(1.0f/PP); }
        __syncthreads();
        float dx0 = x0-cx, dy0 = y0-cy, dz0 = z0-cz;
        float dx1 = x1-cx, dy1 = y1-cy, dz1 = z1-cz;
        sx[tid] = fmaxf(sqrtf(dx0*dx0 + dy0*dy0 + dz0*dz0),
                        sqrtf(dx1*dx1 + dy1*dy1 + dz1*dz1));
        __syncthreads();
        for (int s = 128; s > 0; s >>= 1) {
            if (tid < s) sx[tid] = fmaxf(sx[tid], sx[tid+s]);
            __syncthreads();
        }
        if (tid == 0) {
            g_center[b*3+0] = cx; g_center[b*3+1] = cy; g_center[b*3+2] = cz;
            g_radius[b] = fmaxf(sx[0], 0.001f) * 1.05f;
        }
    } else {
        // transpose + fp16-round: 576 tiles (32x32) per weight
        int ti = blk - BB;
        int wsel = (ti >= 576) ? 1 : 0;
        if (wsel) ti -= 576;
        const float* __restrict__ W = wsel ? Wa2 : Wq2;
        __half* __restrict__ WT = g_WT[wsel];
        const int bx = ti % 24, by = ti / 24;
        const int tx = threadIdx.x & 31, ty = threadIdx.x >> 5;  // 32x8
        __shared__ float tile[32][33];
        int x = bx*32 + tx;   // n
        int y = by*32 + ty;   // k
        #pragma unroll
        for (int j = 0; j < 32; j += 8)
            tile[ty + j][tx] = W[(size_t)(y + j)*DD + x];
        __syncthreads();
        int k = by*32 + tx;
        int n = bx*32 + ty;
        #pragma unroll
        for (int j = 0; j < 32; j += 8)
            WT[(size_t)(n + j)*DD + k] = __float2half_rn(tile[tx][ty + j]);
    }
}

// ---------------- K1: anchor + argmin + raw features + counts ----------------
__global__ void ray_kernel(const float* __restrict__ centers,
                           const float* __restrict__ ray_o,
                           const float* __restrict__ ray_d,
                           const float* __restrict__ ray_t,
                           const float* __restrict__ ray_hit,
                           const float* __restrict__ ray_n) {
    const int b = blockIdx.y;
    const int r = blockIdx.x * 256 + threadIdx.x;
    __shared__ float scx[PP], scy[PP], scz[PP], scc[PP];
    for (int p = threadIdx.x; p < PP; p += 256) {
        float x = centers[(b*PP + p)*3 + 0];
        float y = centers[(b*PP + p)*3 + 1];
        float z = centers[(b*PP + p)*3 + 2];
        scx[p] = x; scy[p] = y; scz[p] = z;
        scc[p] = x*x + y*y + z*z;
    }
    __syncthreads();

    const int gr = b*RR + r;
    float ox = ray_o[gr*3+0], oy = ray_o[gr*3+1], oz = ray_o[gr*3+2];
    float dx = ray_d[gr*3+0], dy = ray_d[gr*3+1], dz = ray_d[gr*3+2];
    float cx = g_center[b*3+0], cy = g_center[b*3+1], cz = g_center[b*3+2];
    float rad = g_radius[b];

    float ocx = ox - cx, ocy = oy - cy, ocz = oz - cz;
    float a  = dx*dx + dy*dy + dz*dz;
    float bq = 2.0f * (ocx*dx + ocy*dy + ocz*dz);
    float cq = (ocx*ocx + ocy*ocy + ocz*ocz) - rad*rad;
    float disc = bq*bq - 4.0f*a*cq;
    bool  has_real = disc > 0.0f;
    float sd = sqrtf(fmaxf(disc, 0.0f));
    float den = 2.0f*a + 1e-6f;
    float t1 = (-bq - sd) / den;
    float t2 = (-bq + sd) / den;
    float t_pos = (t1 > 1e-6f) ? t1 : ((t2 > 1e-6f) ? t2 : 0.0f);
    float t_cl = fmaxf(-bq / den, 0.0f);
    float t = ((t_pos > 0.0f) && has_real) ? t_pos : t_cl;
    float ax = ox + t*dx, ay = oy + t*dy, az = oz + t*dz;

    float aa = ax*ax + ay*ay + az*az;
    float best = 3.402823466e+38f;
    int bi = 0;
    #pragma unroll 4
    for (int p = 0; p < PP; ++p) {
        float dot = ax*scx[p] + ay*scy[p] + az*scz[p];
        float v = aa + scc[p] - 2.0f*dot;
        if (v < best) { best = v; bi = p; }
    }

    float rx = ax - scx[bi], ry = ay - scy[bi], rz = az - scz[bi];
    float* f = &g_feat[(size_t)gr * 11];
    f[0] = rx; f[1] = ry; f[2] = rz;
    f[3] = dx; f[4] = dy; f[5] = dz;
    f[6] = ray_hit[gr];
    f[7] = ray_t[gr];
    f[8] = ray_n[gr*3+0]; f[9] = ray_n[gr*3+1]; f[10] = ray_n[gr*3+2];
    g_assign[gr] = bi;
    atomicAdd(&g_counts[b*PP + bi], 1);
}

// ---------------- K2: per-batch counting-sort scan + scatter ----------------
__global__ __launch_bounds__(512)
void scan_kernel() {
    const int b = blockIdx.x;
    const int tid = threadIdx.x;   // 512
    __shared__ int scur[PP];
    __shared__ int spfx[PP];
    spfx[tid] = g_counts[b*PP + tid];
    __syncthreads();
    if (tid == 0) {
        int run = 0;
        for (int p = 0; p < PP; ++p) {
            int c = spfx[p];
            scur[p] = b*RR + run;
            run += c;
        }
    }
    __syncthreads();
    for (int r = tid; r < RR; r += 512) {
        int gr = b*RR + r;
        int bi = g_assign[gr];
        int slot = atomicAdd(&scur[bi], 1);
        g_order[slot] = gr;
        g_sdstp[slot] = b*PP + bi;
    }
}

// ---------------- K3: layer-1 (q AND a) + GELU via packed f32x2 -> g_H (fp16) --------
__global__ __launch_bounds__(384)
void mlp1_kernel(const float* __restrict__ Wq1, const float* __restrict__ bq1,
                 const float* __restrict__ Wa1, const float* __restrict__ ba1) {
    const int rowBase = blockIdx.x * 32;
    const int tid = threadIdx.x;     // 384; each thread handles cols (2*tid, 2*tid+1)
    __shared__ float sfeat[32*11];
    if (tid < 352) sfeat[tid] = g_feat[(size_t)rowBase*11 + tid];

    const int c0 = tid*2;
    // packed weight pairs (cols c0, c0+1 adjacent in memory, 8B aligned)
    u64t wq[6], wa[11];
    #pragma unroll
    for (int k = 0; k < 6; ++k)
        wq[k] = *reinterpret_cast<const u64t*>(&Wq1[k*DD + c0]);
    #pragma unroll
    for (int k = 0; k < 11; ++k)
        wa[k] = *reinterpret_cast<const u64t*>(&Wa1[k*DD + c0]);
    const u64t bqv = *reinterpret_cast<const u64t*>(&bq1[c0]);
    const u64t bav = *reinterpret_cast<const u64t*>(&ba1[c0]);
    __syncthreads();

    #pragma unroll 2
    for (int r = 0; r < 32; ++r) {
        const float* f = &sfeat[r*11];
        u64t q = bqv, a = bav;
        #pragma unroll
        for (int k = 0; k < 6; ++k) {
            float fv = f[k];
            u64t fvp = pk2(fv, fv);
            FFMA2(q, fvp, wq[k], q);
            FFMA2(a, fvp, wa[k], a);
        }
        #pragma unroll
        for (int k = 6; k < 11; ++k) {
            float fv = f[k];
            u64t fvp = pk2(fv, fv);
            FFMA2(a, fvp, wa[k], a);
        }
        q = gelu2(q);
        a = gelu2(a);
        float q0, q1, a0, a1;
        upk2(q0, q1, q);
        upk2(a0, a1, a);
        size_t off = (size_t)(rowBase + r)*DD + c0;
        *reinterpret_cast<__half2*>(&g_H[0][off]) = __floats2half2_rn(q0, q1);
        *reinterpret_cast<__half2*>(&g_H[1][off]) = __floats2half2_rn(a0, a1);
    }
}

// ---------------- K4: layer-2 fp16 mma GEMM (both MLPs, grid.z) + segmented max ------
// grid = (DD/128 [N, fastest], MM/128 [M, sorted rows], 2 [q,a]); 256 threads; 2 CTA/SM.
__global__ __launch_bounds__(256, 2)
void gemm_kernel(const float* __restrict__ bq2, const float* __restrict__ ba2,
                 unsigned* __restrict__ outEnc) {
    extern __shared__ float smem[];   // STG stages x (A | B) 18432B each; reused as staging
    __shared__ int   srow[128];
    __shared__ int   sdstp[128];
    __shared__ float sb2[128];

    const int tid = threadIdx.x;
    const int wsel = blockIdx.z;
    const int rowBase = blockIdx.y * 128;
    const int colBase = blockIdx.x * 128;
    const __half* __restrict__ H  = g_H[wsel];
    const __half* __restrict__ WT = g_WT[wsel];
    const float* __restrict__ b2 = wsel ? ba2 : bq2;
    unsigned* __restrict__ outp = outEnc + (size_t)wsel*BB*PP*DD;
    const uint32_t sbase = (uint32_t)__cvta_generic_to_shared(smem);

    if (tid < 128) {
        srow[tid]  = g_order[rowBase + tid];
        sdstp[tid] = g_sdstp[rowBase + tid];
        sb2[tid]   = b2[colBase + tid];
    }
    __syncthreads();

    // stage loader: 4 A + 4 B cp.async (16B) per thread (K=64: 8 chunks/row)
    auto load_stage = [&](int s, int kt) {
        const uint32_t aB = sbase + (uint32_t)s * (2*STAGE_BYTES);
        const uint32_t bB = aB + STAGE_BYTES;
        const __half* bSrc = WT + (size_t)colBase*DD + kt*KT;
        #pragma unroll
        for (int i = 0; i < 4; ++i) {
            int idx = tid + i*256;          // 0..1023
            int r = idx >> 3, c = idx & 7;
            const __half* aSrc = H + (size_t)srow[r]*DD + kt*KT + c*8;
            CP_ASYNC16(aB + (uint32_t)(r*HROWB + c*16), aSrc);
        }
        #pragma unroll
        for (int i = 0; i < 4; ++i) {
            int idx = tid + i*256;
            int r = idx >> 3, c = idx & 7;
            CP_ASYNC16(bB + (uint32_t)(r*HROWB + c*16), bSrc + (size_t)r*DD + c*8);
        }
    };

    // prologue: stages 0,1
    load_stage(0, 0); CP_COMMIT();
    load_stage(1, 1); CP_COMMIT();

    const int warp = tid >> 5, lane = tid & 31;
    const int g = lane >> 2, t = lane & 3;
    const int mw = (warp & 3) * 32;   // 4 warps along M
    const int nw = (warp >> 2) * 64;  // 2 warps along N
    const int lrow = ((lane >> 3) & 1) * 8 + (lane & 7);
    const int lkof = (lane >> 4) * 16;

    float acc[2][8][4];
    #pragma unroll
    for (int mf = 0; mf < 2; ++mf)
        #pragma unroll
        for (int nf = 0; nf < 8; ++nf)
            #pragma unroll
            for (int q = 0; q < 4; ++q) acc[mf][nf][q] = 0.0f;

    int sc = 0;                      // stage being computed (0..STG-1)
    for (int kt = 0; kt < NKT; ++kt) {
        if (kt + 2 < NKT) CP_WAIT1(); else CP_WAIT0();
        __syncthreads();             // licenses overwriting stage computed last iter
        if (kt + 2 < NKT) {
            int sl = sc + 2; if (sl >= STG) sl -= STG;
            load_stage(sl, kt + 2);
            CP_COMMIT();
        }

        const uint32_t aS = sbase + (uint32_t)sc * (2*STAGE_BYTES);
        const uint32_t bS = aS + STAGE_BYTES;
        const uint32_t aAddr = aS + (uint32_t)((mw + lrow)*HROWB + lkof);
        const uint32_t bAddr = bS + (uint32_t)((nw + lrow)*HROWB + lkof);

        #pragma unroll
        for (int ks = 0; ks < 4; ++ks) {          // four k16 steps per k64 tile
            const uint32_t ko = (uint32_t)(ks*32);
            uint32_t am[2][4];
            LDSM4(am[0], aAddr + ko);
            LDSM4(am[1], aAddr + 16*HROWB + ko);
            #pragma unroll
            for (int p = 0; p < 4; ++p) {          // 4 n-blocks of 16
                uint32_t bm[4];
                LDSM4(bm, bAddr + (uint32_t)(p*16*HROWB) + ko);
                #pragma unroll
                for (int mf = 0; mf < 2; ++mf) {
                    MMA16816(acc[mf][2*p],     am[mf], bm[0], bm[2]);
                    MMA16816(acc[mf][2*p + 1], am[mf], bm[1], bm[3]);
                }
            }
        }
        if (++sc == STG) sc = 0;
    }

    // ---- epilogue: stage accs (+bias) in smem, segmented max per column ----
    __syncthreads();
    float* Es = smem;   // 128 x 132
    #pragma unroll
    for (int mf = 0; mf < 2; ++mf) {
        int r0 = mw + mf*16 + g;
        #pragma unroll
        for (int nf = 0; nf < 8; ++nf) {
            int c0 = nw + (nf >> 1)*16 + (nf & 1)*8 + 2*t;
            Es[r0*132 + c0]         = acc[mf][nf][0] + sb2[c0];
            Es[r0*132 + c0 + 1]     = acc[mf][nf][1] + sb2[c0 + 1];
            Es[(r0+8)*132 + c0]     = acc[mf][nf][2] + sb2[c0];
            Es[(r0+8)*132 + c0 + 1] = acc[mf][nf][3] + sb2[c0 + 1];
        }
    }
    __syncthreads();

    {
        const int col = tid & 127;
        const int rbase = (tid >> 7) * 64;
        int cur = sdstp[rbase];
        float m = -FLT_MAX;
        #pragma unroll 8
        for (int r = rbase; r < rbase + 64; ++r) {
            int d = sdstp[r];
            float v = Es[r*132 + col];
            if (d != cur) {
                atomicMax(outp + (size_t)cur*DD + colBase + col, encf(m));
                cur = d; m = v;
            } else {
                m = fmaxf(m, v);
            }
        }
        atomicMax(outp + (size_t)cur*DD + colBase + col, encf(m));
    }
}

// ---------------- K5: decode + mask + has_ray ----------------
__global__ void final_kernel(unsigned* __restrict__ outEnc, float* __restrict__ out) {
    int i = blockIdx.x * 256 + threadIdx.x;
    if (i < BB*PP*DD) {
        int bp = i / DD;
        bool has = g_counts[bp] > 0;
        unsigned uq = outEnc[i];
        out[i] = has ? decf(uq) : 0.0f;
        unsigned ua = outEnc[(size_t)BB*PP*DD + i];
        out[(size_t)BB*PP*DD + i] = has ? decf(ua) : 0.0f;
    }
    if (i < BB*PP) {
        out[(size_t)2*BB*PP*DD + i] = (g_counts[i] > 0) ? 1.0f : 0.0f;
    }
}

// ---------------- launch ----------------
extern "C" void kernel_launch(void* const* d_in, const int* in_sizes, int n_in,
                              void* d_out, int out_size) {
    (void)in_sizes; (void)n_in; (void)out_size;
    const float* centers = (const float*)d_in[0];
    const float* ray_o   = (const float*)d_in[1];
    const float* ray_d   = (const float*)d_in[2];
    const float* ray_t   = (const float*)d_in[3];
    const float* ray_hit = (const float*)d_in[4];
    const float* ray_n   = (const float*)d_in[5];
    const float* Wq1 = (const float*)d_in[6];
    const float* bq1 = (const float*)d_in[7];
    const float* Wq2 = (const float*)d_in[8];
    const float* bq2 = (const float*)d_in[9];
    const float* Wa1 = (const float*)d_in[10];
    const float* ba1 = (const float*)d_in[11];
    const float* Wa2 = (const float*)d_in[12];
    const float* ba2 = (const float*)d_in[13];

    unsigned* outEnc = (unsigned*)d_out;
    float*    out    = (float*)d_out;

    static bool attr_set = false;
    if (!attr_set) {
        cudaFuncSetAttribute(gemm_kernel, cudaFuncAttributeMaxDynamicSharedMemorySize, SMEM_BYTES);
        attr_set = true;
    }

    prep_kernel<<<BB + 2*576, 256>>>(centers, Wq2, Wa2, outEnc);
    dim3 gridRay(RR/256, BB);
    ray_kernel<<<gridRay, 256>>>(centers, ray_o, ray_d, ray_t, ray_hit, ray_n);
    scan_kernel<<<BB, 512>>>();

    mlp1_kernel<<<MM/32, 384>>>(Wq1, bq1, Wa1, ba1);

    dim3 gridG(DD/128, MM/128, 2);   // x = N (fastest, L2 A-reuse), z = {q, a}
    gemm_kernel<<<gridG, 256, SMEM_BYTES>>>(bq2, ba2, outEnc);

    final_kernel<<<(BB*PP*DD + 255)/256, 256>>>(outEnc, out);
}

// round 16
// speedup vs baseline: 1.0735x; 1.0047x over previous
#include <cuda_runtime.h>
#include <cuda_fp16.h>
#include <math.h>
#include <float.h>
#include <stdint.h>

#define BB 16
#define PP 512
#define RR 8192
#define DD 768
#define MM (BB*RR)

#define KT 64                   // k per tile (halfs)
#define NKT (DD/KT)             // 12
#define STG 3
#define HROWB 144               // bytes per smem row (128 data + 16 pad); 16B-aligned
#define STAGE_BYTES (128*HROWB) // 18432 B per operand tile
#define SMEM_BYTES  (STG * 2 * STAGE_BYTES)   // 110592 B; also >= 128*132*4 staging

// ---------------- scratch (no-alloc rule: __device__ globals) ----------------
static __device__ float  g_center[BB*3];
static __device__ float  g_radius[BB];
static __device__ float  g_feat[(size_t)MM*11];
static __device__ int    g_assign[MM];
static __device__ int    g_counts[BB*PP];
static __device__ int    g_order[MM];      // sorted slot -> raw ray index
static __device__ int    g_sdstp[MM];      // sorted slot -> global patch id (b*PP+p)
static __device__ __half g_H[2][(size_t)MM*DD];  // fp16 hidden activations (q, a)
static __device__ __half g_WT[2][DD*DD];         // fp16 transposed K-major layer-2 weights

namespace {
struct ForceModuleLoad {
    ForceModuleLoad() {
        void* p = nullptr;
        cudaGetSymbolAddress(&p, g_H);
        (void)p;
    }
};
static ForceModuleLoad g_force_load;
}

// order-preserving float<->uint encoding for atomicMax on floats
__device__ __forceinline__ unsigned encf(float v) {
    unsigned u = __float_as_uint(v);
    return (u & 0x80000000u) ? ~u : (u | 0x80000000u);
}
__device__ __forceinline__ float decf(unsigned u) {
    return (u & 0x80000000u) ? __uint_as_float(u ^ 0x80000000u)
                             : __uint_as_float(~u);
}
#define ENC_NEG 0x00800000u   // encf(-FLT_MAX)

// ---------------- packed f32x2 helpers (sm_100 PTX 8.6) ----------------
typedef unsigned long long u64t;
__device__ __forceinline__ u64t pk2(float lo, float hi) {
    u64t r; asm("mov.b64 %0, {%1, %2};" : "=l"(r) : "f"(lo), "f"(hi)); return r;
}
__device__ __forceinline__ void upk2(float& lo, float& hi, u64t v) {
    asm("mov.b64 {%0, %1}, %2;" : "=f"(lo), "=f"(hi) : "l"(v));
}
#define FFMA2(d, a, b, c) \
    asm("fma.rn.f32x2 %0, %1, %2, %3;" : "=l"(d) : "l"(a), "l"(b), "l"(c))
#define FMUL2(d, a, b) \
    asm("mul.rn.f32x2 %0, %1, %2;" : "=l"(d) : "l"(a), "l"(b))

// Packed GELU (tanh form, HW tanh.approx per lane). Lanes are independent IEEE
// fp32 ops -> bitwise identical to the scalar version.
__device__ __forceinline__ u64t gelu2(u64t x) {
    const u64t c_a   = pk2(0.044715f, 0.044715f);
    const u64t c_one = pk2(1.0f, 1.0f);
    const u64t c_s   = pk2(0.7978845608028654f, 0.7978845608028654f);
    const u64t c_h   = pk2(0.5f, 0.5f);
    u64t x2;  FMUL2(x2, x, x);
    u64t t;   FFMA2(t, c_a, x2, c_one);
    u64t arg; FMUL2(arg, c_s, x); FMUL2(arg, arg, t);
    float a0, a1; upk2(a0, a1, arg);
    float t0, t1;
    asm("tanh.approx.f32 %0, %1;" : "=f"(t0) : "f"(a0));
    asm("tanh.approx.f32 %0, %1;" : "=f"(t1) : "f"(a1));
    u64t th = pk2(t0, t1);
    u64t hx; FMUL2(hx, c_h, x);
    u64t r;  FFMA2(r, hx, th, hx);
    return r;
}

#define CP_ASYNC16(dst, src) \
    asm volatile("cp.async.cg.shared.global [%0], [%1], 16;" :: "r"(dst), "l"(src) : "memory")
#define CP_COMMIT() asm volatile("cp.async.commit_group;" ::: "memory")
#define CP_WAIT1()  asm volatile("cp.async.wait_group 1;" ::: "memory")
#define CP_WAIT0()  asm volatile("cp.async.wait_group 0;" ::: "memory")

#define LDSM4(r, addr) \
    asm volatile("ldmatrix.sync.aligned.m8n8.x4.shared.b16 {%0,%1,%2,%3}, [%4];" \
        : "=r"((r)[0]), "=r"((r)[1]), "=r"((r)[2]), "=r"((r)[3]) : "r"(addr))

#define MMA16816(acc, a, b0, b1) \
    asm volatile( \
        "mma.sync.aligned.m16n8k16.row.col.f32.f16.f16.f32 " \
        "{%0,%1,%2,%3}, {%4,%5,%6,%7}, {%8,%9}, {%0,%1,%2,%3};\n" \
        : "+f"((acc)[0]), "+f"((acc)[1]), "+f"((acc)[2]), "+f"((acc)[3]) \
        : "r"((a)[0]), "r"((a)[1]), "r"((a)[2]), "r"((a)[3]), "r"(b0), "r"(b1))

// ---------------- K0: prep = proxy (blocks 0..15) + weight transposes + init ---------
__global__ __launch_bounds__(256)
void prep_kernel(const float* __restrict__ centers,
                 const float* __restrict__ Wq2, const float* __restrict__ Wa2,
                 unsigned* __restrict__ outEnc) {
    const int blk = blockIdx.x;
    // grid-stride uint4 init of outEnc (runs strictly before any gemm)
    {
        const size_t nvec = (size_t)2*BB*PP*DD / 4;   // 3,145,728 uint4
        uint4 fill = make_uint4(ENC_NEG, ENC_NEG, ENC_NEG, ENC_NEG);
        size_t stride = (size_t)gridDim.x * 256;
        for (size_t i = (size_t)blk*256 + threadIdx.x; i < nvec; i += stride)
            reinterpret_cast<uint4*>(outEnc)[i] = fill;
    }
    if (blk < BB) {
        const int b = blk;
        const int tid = threadIdx.x;
        __shared__ float sx[256], sy[256], sz[256];
        float x0 = centers[(b*PP + tid)*3 + 0];
        float y0 = centers[(b*PP + tid)*3 + 1];
        float z0 = centers[(b*PP + tid)*3 + 2];
        float x1 = centers[(b*PP + tid + 256)*3 + 0];
        float y1 = centers[(b*PP + tid + 256)*3 + 1];
        float z1 = centers[(b*PP + tid + 256)*3 + 2];
        sx[tid] = x0 + x1; sy[tid] = y0 + y1; sz[tid] = z0 + z1;
        g_counts[b*PP + tid] = 0;
        g_counts[b*PP + tid + 256] = 0;
        __syncthreads();
        for (int s = 128; s > 0; s >>= 1) {
            if (tid < s) { sx[tid] += sx[tid+s]; sy[tid] += sy[tid+s]; sz[tid] += sz[tid+s]; }
            __syncthreads();
        }
        __shared__ float cx, cy, cz;
        if (tid == 0) { cx = sx[0]*(1.0f/PP); cy = sy[0]*(1.0f/PP); cz = sz[0]*(1.0f/PP); }
        __syncthreads();
        float dx0 = x0-cx, dy0 = y0-cy, dz0 = z0-cz;
        float dx1 = x1-cx, dy1 = y1-cy, dz1 = z1-cz;
        sx[tid] = fmaxf(sqrtf(dx0*dx0 + dy0*dy0 + dz0*dz0),
                        sqrtf(dx1*dx1 + dy1*dy1 + dz1*dz1));
        __syncthreads();
        for (int s = 128; s > 0; s >>= 1) {
            if (tid < s) sx[tid] = fmaxf(sx[tid], sx[tid+s]);
            __syncthreads();
        }
        if (tid == 0) {
            g_center[b*3+0] = cx; g_center[b*3+1] = cy; g_center[b*3+2] = cz;
            g_radius[b] = fmaxf(sx[0], 0.001f) * 1.05f;
        }
    } else {
        // transpose + fp16-round: 576 tiles (32x32) per weight
        int ti = blk - BB;
        int wsel = (ti >= 576) ? 1 : 0;
        if (wsel) ti -= 576;
        const float* __restrict__ W = wsel ? Wa2 : Wq2;
        __half* __restrict__ WT = g_WT[wsel];
        const int bx = ti % 24, by = ti / 24;
        const int tx = threadIdx.x & 31, ty = threadIdx.x >> 5;  // 32x8
        __shared__ float tile[32][33];
        int x = bx*32 + tx;   // n
        int y = by*32 + ty;   // k
        #pragma unroll
        for (int j = 0; j < 32; j += 8)
            tile[ty + j][tx] = W[(size_t)(y + j)*DD + x];
        __syncthreads();
        int k = by*32 + tx;
        int n = bx*32 + ty;
        #pragma unroll
        for (int j = 0; j < 32; j += 8)
            WT[(size_t)(n + j)*DD + k] = __float2half_rn(tile[tx][ty + j]);
    }
}

// ---------------- K1: anchor + argmin + raw features + counts ----------------
__global__ void ray_kernel(const float* __restrict__ centers,
                           const float* __restrict__ ray_o,
                           const float* __restrict__ ray_d,
                           const float* __restrict__ ray_t,
                           const float* __restrict__ ray_hit,
                           const float* __restrict__ ray_n) {
    const int b = blockIdx.y;
    const int r = blockIdx.x * 256 + threadIdx.x;
    __shared__ float scx[PP], scy[PP], scz[PP], scc[PP];
    for (int p = threadIdx.x; p < PP; p += 256) {
        float x = centers[(b*PP + p)*3 + 0];
        float y = centers[(b*PP + p)*3 + 1];
        float z = centers[(b*PP + p)*3 + 2];
        scx[p] = x; scy[p] = y; scz[p] = z;
        scc[p] = x*x + y*y + z*z;
    }
    __syncthreads();

    const int gr = b*RR + r;
    float ox = ray_o[gr*3+0], oy = ray_o[gr*3+1], oz = ray_o[gr*3+2];
    float dx = ray_d[gr*3+0], dy = ray_d[gr*3+1], dz = ray_d[gr*3+2];
    float cx = g_center[b*3+0], cy = g_center[b*3+1], cz = g_center[b*3+2];
    float rad = g_radius[b];

    float ocx = ox - cx, ocy = oy - cy, ocz = oz - cz;
    float a  = dx*dx + dy*dy + dz*dz;
    float bq = 2.0f * (ocx*dx + ocy*dy + ocz*dz);
    float cq = (ocx*ocx + ocy*ocy + ocz*ocz) - rad*rad;
    float disc = bq*bq - 4.0f*a*cq;
    bool  has_real = disc > 0.0f;
    float sd = sqrtf(fmaxf(disc, 0.0f));
    float den = 2.0f*a + 1e-6f;
    float t1 = (-bq - sd) / den;
    float t2 = (-bq + sd) / den;
    float t_pos = (t1 > 1e-6f) ? t1 : ((t2 > 1e-6f) ? t2 : 0.0f);
    float t_cl = fmaxf(-bq / den, 0.0f);
    float t = ((t_pos > 0.0f) && has_real) ? t_pos : t_cl;
    float ax = ox + t*dx, ay = oy + t*dy, az = oz + t*dz;

    float aa = ax*ax + ay*ay + az*az;
    float best = 3.402823466e+38f;
    int bi = 0;
    #pragma unroll 4
    for (int p = 0; p < PP; ++p) {
        float dot = ax*scx[p] + ay*scy[p] + az*scz[p];
        float v = aa + scc[p] - 2.0f*dot;
        if (v < best) { best = v; bi = p; }
    }

    float rx = ax - scx[bi], ry = ay - scy[bi], rz = az - scz[bi];
    float* f = &g_feat[(size_t)gr * 11];
    f[0] = rx; f[1] = ry; f[2] = rz;
    f[3] = dx; f[4] = dy; f[5] = dz;
    f[6] = ray_hit[gr];
    f[7] = ray_t[gr];
    f[8] = ray_n[gr*3+0]; f[9] = ray_n[gr*3+1]; f[10] = ray_n[gr*3+2];
    g_assign[gr] = bi;
    atomicAdd(&g_counts[b*PP + bi], 1);
}

// ---------------- K2: per-batch counting-sort scan + scatter ----------------
__global__ __launch_bounds__(512)
void scan_kernel() {
    const int b = blockIdx.x;
    const int tid = threadIdx.x;   // 512
    __shared__ int scur[PP];
    __shared__ int spfx[PP];
    spfx[tid] = g_counts[b*PP + tid];
    __syncthreads();
    if (tid == 0) {
        int run = 0;
        for (int p = 0; p < PP; ++p) {
            int c = spfx[p];
            scur[p] = b*RR + run;
            run += c;
        }
    }
    __syncthreads();
    for (int r = tid; r < RR; r += 512) {
        int gr = b*RR + r;
        int bi = g_assign[gr];
        int slot = atomicAdd(&scur[bi], 1);
        g_order[slot] = gr;
        g_sdstp[slot] = b*PP + bi;
    }
}

// ---------------- K3: layer-1 (q AND a) + GELU via packed f32x2 -> g_H (fp16) --------
// sfeat stored pre-duplicated as (f,f) u64 pairs: row loop = 1 broadcast LDS.64
// per feature, feeding FFMA2 directly (no per-row re-packing).
__global__ __launch_bounds__(384)
void mlp1_kernel(const float* __restrict__ Wq1, const float* __restrict__ bq1,
                 const float* __restrict__ Wa1, const float* __restrict__ ba1) {
    const int rowBase = blockIdx.x * 32;
    const int tid = threadIdx.x;     // 384; each thread handles cols (2*tid, 2*tid+1)
    __shared__ u64t sfeat2[32*11];
    if (tid < 352) {
        float f = g_feat[(size_t)rowBase*11 + tid];
        sfeat2[tid] = pk2(f, f);
    }

    const int c0 = tid*2;
    // packed weight pairs (cols c0, c0+1 adjacent in memory, 8B aligned)
    u64t wq[6], wa[11];
    #pragma unroll
    for (int k = 0; k < 6; ++k)
        wq[k] = *reinterpret_cast<const u64t*>(&Wq1[k*DD + c0]);
    #pragma unroll
    for (int k = 0; k < 11; ++k)
        wa[k] = *reinterpret_cast<const u64t*>(&Wa1[k*DD + c0]);
    const u64t bqv = *reinterpret_cast<const u64t*>(&bq1[c0]);
    const u64t bav = *reinterpret_cast<const u64t*>(&ba1[c0]);
    __syncthreads();

    #pragma unroll 2
    for (int r = 0; r < 32; ++r) {
        const u64t* f = &sfeat2[r*11];
        u64t q = bqv, a = bav;
        #pragma unroll
        for (int k = 0; k < 6; ++k) {
            u64t fvp = f[k];
            FFMA2(q, fvp, wq[k], q);
            FFMA2(a, fvp, wa[k], a);
        }
        #pragma unroll
        for (int k = 6; k < 11; ++k) {
            FFMA2(a, f[k], wa[k], a);
        }
        q = gelu2(q);
        a = gelu2(a);
        float q0, q1, a0, a1;
        upk2(q0, q1, q);
        upk2(a0, a1, a);
        size_t off = (size_t)(rowBase + r)*DD + c0;
        *reinterpret_cast<__half2*>(&g_H[0][off]) = __floats2half2_rn(q0, q1);
        *reinterpret_cast<__half2*>(&g_H[1][off]) = __floats2half2_rn(a0, a1);
    }
}

// ---------------- K4: layer-2 fp16 mma GEMM (both MLPs, grid.z) + segmented max ------
// grid = (DD/128 [N, fastest], MM/128 [M, sorted rows], 2 [q,a]); 256 threads; 2 CTA/SM.
__global__ __launch_bounds__(256, 2)
void gemm_kernel(const float* __restrict__ bq2, const float* __restrict__ ba2,
                 unsigned* __restrict__ outEnc) {
    extern __shared__ float smem[];   // STG stages x (A | B) 18432B each; reused as staging
    __shared__ int   srow[128];
    __shared__ int   sdstp[128];
    __shared__ float sb2[128];

    const int tid = threadIdx.x;
    const int wsel = blockIdx.z;
    const int rowBase = blockIdx.y * 128;
    const int colBase = blockIdx.x * 128;
    const __half* __restrict__ H  = g_H[wsel];
    const __half* __restrict__ WT = g_WT[wsel];
    const float* __restrict__ b2 = wsel ? ba2 : bq2;
    unsigned* __restrict__ outp = outEnc + (size_t)wsel*BB*PP*DD;
    const uint32_t sbase = (uint32_t)__cvta_generic_to_shared(smem);

    if (tid < 128) {
        srow[tid]  = g_order[rowBase + tid];
        sdstp[tid] = g_sdstp[rowBase + tid];
        sb2[tid]   = b2[colBase + tid];
    }
    __syncthreads();

    // stage loader: 4 A + 4 B cp.async (16B) per thread (K=64: 8 chunks/row)
    auto load_stage = [&](int s, int kt) {
        const uint32_t aB = sbase + (uint32_t)s * (2*STAGE_BYTES);
        const uint32_t bB = aB + STAGE_BYTES;
        const __half* bSrc = WT + (size_t)colBase*DD + kt*KT;
        #pragma unroll
        for (int i = 0; i < 4; ++i) {
            int idx = tid + i*256;          // 0..1023
            int r = idx >> 3, c = idx & 7;
            const __half* aSrc = H + (size_t)srow[r]*DD + kt*KT + c*8;
            CP_ASYNC16(aB + (uint32_t)(r*HROWB + c*16), aSrc);
        }
        #pragma unroll
        for (int i = 0; i < 4; ++i) {
            int idx = tid + i*256;
            int r = idx >> 3, c = idx & 7;
            CP_ASYNC16(bB + (uint32_t)(r*HROWB + c*16), bSrc + (size_t)r*DD + c*8);
        }
    };

    // prologue: stages 0,1
    load_stage(0, 0); CP_COMMIT();
    load_stage(1, 1); CP_COMMIT();

    const int warp = tid >> 5, lane = tid & 31;
    const int g = lane >> 2, t = lane & 3;
    const int mw = (warp & 3) * 32;   // 4 warps along M
    const int nw = (warp >> 2) * 64;  // 2 warps along N
    const int lrow = ((lane >> 3) & 1) * 8 + (lane & 7);
    const int lkof = (lane >> 4) * 16;

    float acc[2][8][4];
    #pragma unroll
    for (int mf = 0; mf < 2; ++mf)
        #pragma unroll
        for (int nf = 0; nf < 8; ++nf)
            #pragma unroll
            for (int q = 0; q < 4; ++q) acc[mf][nf][q] = 0.0f;

    int sc = 0;                      // stage being computed (0..STG-1)
    for (int kt = 0; kt < NKT; ++kt) {
        if (kt + 2 < NKT) CP_WAIT1(); else CP_WAIT0();
        __syncthreads();             // licenses overwriting stage computed last iter
        if (kt + 2 < NKT) {
            int sl = sc + 2; if (sl >= STG) sl -= STG;
            load_stage(sl, kt + 2);
            CP_COMMIT();
        }

        const uint32_t aS = sbase + (uint32_t)sc * (2*STAGE_BYTES);
        const uint32_t bS = aS + STAGE_BYTES;
        const uint32_t aAddr = aS + (uint32_t)((mw + lrow)*HROWB + lkof);
        const uint32_t bAddr = bS + (uint32_t)((nw + lrow)*HROWB + lkof);

        #pragma unroll
        for (int ks = 0; ks < 4; ++ks) {          // four k16 steps per k64 tile
            const uint32_t ko = (uint32_t)(ks*32);
            uint32_t am[2][4];
            LDSM4(am[0], aAddr + ko);
            LDSM4(am[1], aAddr + 16*HROWB + ko);
            #pragma unroll
            for (int p = 0; p < 4; ++p) {          // 4 n-blocks of 16
                uint32_t bm[4];
                LDSM4(bm, bAddr + (uint32_t)(p*16*HROWB) + ko);
                #pragma unroll
                for (int mf = 0; mf < 2; ++mf) {
                    MMA16816(acc[mf][2*p],     am[mf], bm[0], bm[2]);
                    MMA16816(acc[mf][2*p + 1], am[mf], bm[1], bm[3]);
                }
            }
        }
        if (++sc == STG) sc = 0;
    }

    // ---- epilogue: stage accs (+bias) in smem, segmented max per column ----
    __syncthreads();
    float* Es = smem;   // 128 x 132
    #pragma unroll
    for (int mf = 0; mf < 2; ++mf) {
        int r0 = mw + mf*16 + g;
        #pragma unroll
        for (int nf = 0; nf < 8; ++nf) {
            int c0 = nw + (nf >> 1)*16 + (nf & 1)*8 + 2*t;
            Es[r0*132 + c0]         = acc[mf][nf][0] + sb2[c0];
            Es[r0*132 + c0 + 1]     = acc[mf][nf][1] + sb2[c0 + 1];
            Es[(r0+8)*132 + c0]     = acc[mf][nf][2] + sb2[c0];
            Es[(r0+8)*132 + c0 + 1] = acc[mf][nf][3] + sb2[c0 + 1];
        }
    }
    __syncthreads();

    {
        const int col = tid & 127;
        const int rbase = (tid >> 7) * 64;
        int cur = sdstp[rbase];
        float m = -FLT_MAX;
        #pragma unroll 8
        for (int r = rbase; r < rbase + 64; ++r) {
            int d = sdstp[r];
            float v = Es[r*132 + col];
            if (d != cur) {
                atomicMax(outp + (size_t)cur*DD + colBase + col, encf(m));
                cur = d; m = v;
            } else {
                m = fmaxf(m, v);
            }
        }
        atomicMax(outp + (size_t)cur*DD + colBase + col, encf(m));
    }
}

// ---------------- K5: decode + mask + has_ray ----------------
__global__ void final_kernel(unsigned* __restrict__ outEnc, float* __restrict__ out) {
    int i = blockIdx.x * 256 + threadIdx.x;
    if (i < BB*PP*DD) {
        int bp = i / DD;
        bool has = g_counts[bp] > 0;
        unsigned uq = outEnc[i];
        out[i] = has ? decf(uq) : 0.0f;
        unsigned ua = outEnc[(size_t)BB*PP*DD + i];
        out[(size_t)BB*PP*DD + i] = has ? decf(ua) : 0.0f;
    }
    if (i < BB*PP) {
        out[(size_t)2*BB*PP*DD + i] = (g_counts[i] > 0) ? 1.0f : 0.0f;
    }
}

// ---------------- launch ----------------
extern "C" void kernel_launch(void* const* d_in, const int* in_sizes, int n_in,
                              void* d_out, int out_size) {
    (void)in_sizes; (void)n_in; (void)out_size;
    const float* centers = (const float*)d_in[0];
    const float* ray_o   = (const float*)d_in[1];
    const float* ray_d   = (const float*)d_in[2];
    const float* ray_t   = (const float*)d_in[3];
    const float* ray_hit = (const float*)d_in[4];
    const float* ray_n   = (const float*)d_in[5];
    const float* Wq1 = (const float*)d_in[6];
    const float* bq1 = (const float*)d_in[7];
    const float* Wq2 = (const float*)d_in[8];
    const float* bq2 = (const float*)d_in[9];
    const float* Wa1 = (const float*)d_in[10];
    const float* ba1 = (const float*)d_in[11];
    const float* Wa2 = (const float*)d_in[12];
    const float* ba2 = (const float*)d_in[13];

    unsigned* outEnc = (unsigned*)d_out;
    float*    out    = (float*)d_out;

    static bool attr_set = false;
    if (!attr_set) {
        cudaFuncSetAttribute(gemm_kernel, cudaFuncAttributeMaxDynamicSharedMemorySize, SMEM_BYTES);
        attr_set = true;
    }

    prep_kernel<<<BB + 2*576, 256>>>(centers, Wq2, Wa2, outEnc);
    dim3 gridRay(RR/256, BB);
    ray_kernel<<<gridRay, 256>>>(centers, ray_o, ray_d, ray_t, ray_hit, ray_n);
    scan_kernel<<<BB, 512>>>();

    mlp1_kernel<<<MM/32, 384>>>(Wq1, bq1, Wa1, ba1);

    dim3 gridG(DD/128, MM/128, 2);   // x = N (fastest, L2 A-reuse), z = {q, a}
    gemm_kernel<<<gridG, 256, SMEM_BYTES>>>(bq2, ba2, outEnc);

    final_kernel<<<(BB*PP*DD + 255)/256, 256>>>(outEnc, out);
}